// round 5
// baseline (speedup 1.0000x reference)
#include <cuda_runtime.h>

// ---------------------------------------------------------------------------
// GNNMLP fused kernel, round 4 = round 3 structure + accurate tanhf.
//  * duplicated activation storage (x,x): broadcast LDS.128 directly yields
//    packed f32x2 operands -> zero packing MOVs in the hot loop
//  * interleaved weight layout (k,k+1 column-pairs contiguous) -> 1 LDS.128
//    per matrix per 2-k-step
//  * 1 group per warp, 16 warps/CTA (512 thr), MLP buffers alias OBS region
//  * libm tanhf (R3's MUFU tanh broke rel_err at small outputs: 1.37e-3)
// ---------------------------------------------------------------------------

#define G_TOT   131072
#define THREADS 512
#define WARPS   16
#define GPC     WARPS          // 1 group per warp per iteration

typedef unsigned long long ull;

// ---- packed f32x2 helpers --------------------------------------------------
__device__ __forceinline__ float2 upk(ull v) {
    float2 r; asm("mov.b64 {%0,%1}, %2;" : "=f"(r.x), "=f"(r.y) : "l"(v)); return r;
}
__device__ __forceinline__ ull f2fma(ull a, ull b, ull c) {
    ull d; asm("fma.rn.f32x2 %0, %1, %2, %3;" : "=l"(d) : "l"(a), "l"(b), "l"(c));
    return d;
}
__device__ __forceinline__ void lds128(ull& a, ull& b, unsigned addr) {
    asm volatile("ld.shared.v2.u64 {%0,%1}, [%2];" : "=l"(a), "=l"(b) : "r"(addr));
}
__device__ __forceinline__ void sts128(unsigned addr, float a, float b, float c, float d) {
    asm volatile("st.shared.v4.f32 [%0], {%1,%2,%3,%4};"
                 :: "r"(addr), "f"(a), "f"(b), "f"(c), "f"(d));
}

// ---- SMEM layout (float offsets) ------------------------------------------
// Weights stored INTERLEAVED: float4 j=(kh*32+cp) = (W[2kh][2cp],W[2kh][2cp+1],
//                                                    W[2kh+1][2cp],W[2kh+1][2cp+1])
#define OFF_WP1  0
#define OFF_WS1  4096
#define OFF_WP2  8192
#define OFF_WS2  12288
#define OFF_MW1  16384
#define OFF_MW2  24576
#define OFF_MW3  32768
#define OFF_BIAS 40960
//   BIAS: +0 bp1 +64 b1 +128 bp2 +192 b2 +256 Mb1(128) +384 Mb2(128)
//         +512 Mb3(128) +640 MW4(256) +896 Mb4(4)
#define OFF_WS_  41984
#define WARP_WS  896           // OBSdup 768 | NBdup 128 ; RES/XA/XB alias OBS
#define SMEM_FLOATS (OFF_WS_ + WARPS * WARP_WS)   // 56320
#define SMEM_BYTES  (SMEM_FLOATS * 4)             // 225280 < 232448

struct Params {
    const float *obs, *Wp1, *bp1, *Ws1, *Wn1, *b1;
    const float *Wp2, *bp2, *Ws2, *Wn2, *b2;
    const float *MW1, *Mb1, *MW2, *Mb2, *MW3, *Mb3, *MW4, *Mb4;
    float *out;
};

extern __shared__ float smem[];

__device__ __forceinline__ void cp4(float* dst, const float* src, int n) {
    for (int i = threadIdx.x; i < (n >> 2); i += THREADS)
        ((float4*)dst)[i] = ((const float4*)src)[i];
}
// interleave one 64x64 matrix into dst
__device__ __forceinline__ void cp_i(float* dst, const float* src) {
    const float2* s2 = (const float2*)src;
    float4* d4 = (float4*)dst;
    for (int j = threadIdx.x; j < 1024; j += THREADS) {
        int kh = j >> 5, cp = j & 31;
        float2 a = s2[(2 * kh) * 32 + cp];
        float2 b = s2[(2 * kh + 1) * 32 + cp];
        d4[j] = make_float4(a.x, a.y, b.x, b.y);
    }
}

// ---- one SAGE-pool conv, 1 group (6 rows), dup layouts ---------------------
// rows: dup [6][128] (byte addr). Lane owns output cols {2*lane, 2*lane+1}.
template<bool FIRST>
__device__ __forceinline__ void sage(unsigned rows, unsigned nb, unsigned res,
                                     unsigned wpA, unsigned wsA,
                                     const float* __restrict__ gWn,
                                     const float* bp, const float* bb, int lane)
{
    ull aP[6], aS[6];
    ull bpv = *(const ull*)(bp + 2 * lane);
    #pragma unroll
    for (int r = 0; r < 6; r++) { aP[r] = bpv; aS[r] = 0ull; }

    const unsigned wpL = wpA + lane * 16;
    const unsigned wsL = wsA + lane * 16;

    #pragma unroll 4
    for (int kh = 0; kh < 32; kh++) {
        ull wp0, wp1, ws0, ws1;
        lds128(wp0, wp1, wpL + kh * 512);
        lds128(ws0, ws1, wsL + kh * 512);
        #pragma unroll
        for (int r = 0; r < 6; r++) {
            ull b0, b1;                               // (x_k,x_k),(x_k1,x_k1)
            lds128(b0, b1, rows + r * 512 + kh * 16); // warp-broadcast
            aP[r] = f2fma(b1, wp1, f2fma(b0, wp0, aP[r]));
            aS[r] = f2fma(b1, ws1, f2fma(b0, ws0, aS[r]));
        }
    }

    // neigh = max over 6 agents of relu(p); relu folded via 0-init
    float mx = 0.f, my = 0.f;
    #pragma unroll
    for (int r = 0; r < 6; r++) {
        float2 p = upk(aP[r]);
        mx = fmaxf(mx, p.x); my = fmaxf(my, p.y);
    }
    sts128(nb + lane * 16, mx, mx, my, my);
    __syncwarp();

    // nn = neigh @ Wn (Wn streamed from global/L2; uniform lines across warps)
    ull nn = 0ull;
    const ull* wn = (const ull*)gWn + lane;
    #pragma unroll 4
    for (int kh = 0; kh < 32; kh++) {
        ull x0, x1;
        lds128(x0, x1, nb + kh * 16);
        ull w0 = wn[(2 * kh) * 32];
        ull w1 = wn[(2 * kh + 1) * 32];
        nn = f2fma(x1, w1, f2fma(x0, w0, nn));
    }
    float2 bbv = *(const float2*)(bb + 2 * lane);
    float2 n = upk(nn);
    n.x += bbv.x; n.y += bbv.y;

    if (FIRST) {
        #pragma unroll
        for (int r = 0; r < 6; r++) {
            float2 s = upk(aS[r]);
            float v0 = tanhf(s.x + n.x);
            float v1 = tanhf(s.y + n.y);
            sts128(rows + r * 512 + lane * 16, v0, v0, v1, v1);   // dup store
        }
        __syncwarp();
    } else {
        float sx = 0.f, sy = 0.f;
        #pragma unroll
        for (int r = 0; r < 6; r++) {
            float2 s = upk(aS[r]); sx += s.x; sy += s.y;
        }
        sx = sx * (1.f / 6.f) + n.x;
        sy = sy * (1.f / 6.f) + n.y;
        sts128(res + lane * 16, sx, sx, sy, sy);                  // dup store
        __syncwarp();
    }
}

// ---- one MLP layer (dup in -> relu -> dup out) -----------------------------
__device__ __forceinline__ void mlp(unsigned in, unsigned out, unsigned wA,
                                    const float* b, int lane)
{
    ull a = *(const ull*)(b + 2 * lane);
    const unsigned wL = wA + lane * 16;
    #pragma unroll 4
    for (int kh = 0; kh < 32; kh++) {
        ull x0, x1, w0, w1;
        lds128(x0, x1, in + kh * 16);      // broadcast dup input
        lds128(w0, w1, wL + kh * 512);     // interleaved weights
        a = f2fma(x1, w1, f2fma(x0, w0, a));
    }
    float2 v = upk(a);
    float r0 = fmaxf(v.x, 0.f), r1 = fmaxf(v.y, 0.f);
    sts128(out + lane * 16, r0, r0, r1, r1);
    __syncwarp();
}

__global__ void __launch_bounds__(THREADS, 1) gnn_kernel(Params P)
{
    // weights -> SMEM once per persistent CTA (interleaved for the hot loops)
    cp_i(smem + OFF_WP1, P.Wp1);
    cp_i(smem + OFF_WS1, P.Ws1);
    cp_i(smem + OFF_WP2, P.Wp2);
    cp_i(smem + OFF_WS2, P.Ws2);
    cp_i(smem + OFF_MW1,        P.MW1);
    cp_i(smem + OFF_MW1 + 4096, P.MW1 + 4096);
    cp_i(smem + OFF_MW2,        P.MW2);
    cp_i(smem + OFF_MW2 + 4096, P.MW2 + 4096);
    cp_i(smem + OFF_MW3,        P.MW3);
    cp_i(smem + OFF_MW3 + 4096, P.MW3 + 4096);
    cp4(smem + OFF_BIAS +   0, P.bp1, 64);
    cp4(smem + OFF_BIAS +  64, P.b1,  64);
    cp4(smem + OFF_BIAS + 128, P.bp2, 64);
    cp4(smem + OFF_BIAS + 192, P.b2,  64);
    cp4(smem + OFF_BIAS + 256, P.Mb1, 128);
    cp4(smem + OFF_BIAS + 384, P.Mb2, 128);
    cp4(smem + OFF_BIAS + 512, P.Mb3, 128);
    cp4(smem + OFF_BIAS + 640, P.MW4, 256);
    cp4(smem + OFF_BIAS + 896, P.Mb4, 4);
    __syncthreads();

    const int lane = threadIdx.x & 31;
    const int warp = threadIdx.x >> 5;

    const unsigned sb  = (unsigned)__cvta_generic_to_shared(smem);
    const unsigned wsA = sb + (OFF_WS_ + warp * WARP_WS) * 4;
    const unsigned OBS = wsA;                 // dup [6][128] floats
    const unsigned NB  = wsA + 768 * 4;       // dup [128]
    const unsigned RES = OBS;                 // alias (safe: written post-reads)
    const unsigned XA  = OBS + 128 * 4;
    const unsigned XB  = OBS + 256 * 4;
    const unsigned WP1 = sb + OFF_WP1 * 4, WS1 = sb + OFF_WS1 * 4;
    const unsigned WP2 = sb + OFF_WP2 * 4, WS2 = sb + OFF_WS2 * 4;
    const unsigned MW1 = sb + OFF_MW1 * 4, MW2 = sb + OFF_MW2 * 4;
    const unsigned MW3 = sb + OFF_MW3 * 4;
    const float* BIAS = smem + OFF_BIAS;
    float* XAf = smem + OFF_WS_ + warp * WARP_WS + 128;

    for (int g = blockIdx.x * GPC + warp; g < G_TOT; g += gridDim.x * GPC) {
        __syncwarp();
        // stage obs duplicated: float2 (a,b) -> float4 (a,a,b,b)
        {
            const float2* s2 = (const float2*)(P.obs + (size_t)g * 384);
            #pragma unroll
            for (int i = 0; i < 6; i++) {
                int m = lane + 32 * i;
                float2 a = s2[m];
                sts128(OBS + m * 16, a.x, a.x, a.y, a.y);
            }
        }
        __syncwarp();

        sage<true >(OBS, NB, RES, WP1, WS1, P.Wn1, BIAS + 0,   BIAS + 64,  lane);
        sage<false>(OBS, NB, RES, WP2, WS2, P.Wn2, BIAS + 128, BIAS + 192, lane);

        float o00, o01, o10, o11;
        #pragma unroll
        for (int t = 0; t < 2; t++) {
            mlp(RES, XA, MW1 + t * 16384, BIAS + 256 + t * 64, lane);
            mlp(XA,  XB, MW2 + t * 16384, BIAS + 384 + t * 64, lane);
            mlp(XB,  XA, MW3 + t * 16384, BIAS + 512 + t * 64, lane);

            // final [64]->2 head via warp reduction (XA is dup layout)
            const float* w4 = BIAS + 640 + t * 128;   // MW4[t][k][o]
            float x0 = XAf[4 * lane], x1 = XAf[4 * lane + 2];
            float s0 = x0 * w4[4 * lane]     + x1 * w4[4 * lane + 2];
            float s1 = x0 * w4[4 * lane + 1] + x1 * w4[4 * lane + 3];
            #pragma unroll
            for (int off = 16; off; off >>= 1) {
                s0 += __shfl_xor_sync(0xffffffffu, s0, off);
                s1 += __shfl_xor_sync(0xffffffffu, s1, off);
            }
            float v0 = tanhf(s0 + BIAS[896 + t * 2 + 0]);
            float v1 = tanhf(s1 + BIAS[896 + t * 2 + 1]);
            if (t == 0) { o00 = v0; o01 = v1; } else { o10 = v0; o11 = v1; }
            __syncwarp();
        }

        // out[g][a][:] : agents 0..4 -> type0 (o00,o01), agent 5 -> type1
        if (lane < 3) {
            float4 v = (lane < 2) ? make_float4(o00, o01, o00, o01)
                                  : make_float4(o00, o01, o10, o11);
            ((float4*)(P.out + (size_t)g * 12))[lane] = v;
        }
    }
}

extern "C" void kernel_launch(void* const* d_in, const int* in_sizes, int n_in,
                              void* d_out, int out_size)
{
    (void)in_sizes; (void)n_in; (void)out_size;
    Params P;
    P.obs = (const float*)d_in[0];
    P.Wp1 = (const float*)d_in[1];  P.bp1 = (const float*)d_in[2];
    P.Ws1 = (const float*)d_in[3];  P.Wn1 = (const float*)d_in[4];
    P.b1  = (const float*)d_in[5];
    P.Wp2 = (const float*)d_in[6];  P.bp2 = (const float*)d_in[7];
    P.Ws2 = (const float*)d_in[8];  P.Wn2 = (const float*)d_in[9];
    P.b2  = (const float*)d_in[10];
    P.MW1 = (const float*)d_in[11]; P.Mb1 = (const float*)d_in[12];
    P.MW2 = (const float*)d_in[13]; P.Mb2 = (const float*)d_in[14];
    P.MW3 = (const float*)d_in[15]; P.Mb3 = (const float*)d_in[16];
    P.MW4 = (const float*)d_in[17]; P.Mb4 = (const float*)d_in[18];
    P.out = (float*)d_out;

    int dev = 0, nsm = 148;
    cudaGetDevice(&dev);
    cudaDeviceGetAttribute(&nsm, cudaDevAttrMultiProcessorCount, dev);
    cudaFuncSetAttribute(gnn_kernel, cudaFuncAttributeMaxDynamicSharedMemorySize,
                         SMEM_BYTES);
    gnn_kernel<<<nsm, THREADS, SMEM_BYTES>>>(P);
}